// round 4
// baseline (speedup 1.0000x reference)
#include <cuda_runtime.h>

// LengthRegulator, fixed shapes: B=32, T=512, D=384, ML=4096.
// out[b,f,:]   = x[b, clip(searchsorted_right(cum(dur[b]), f), 0, T-1), :] * (f < total_b)
// mel_pos[b,f] = (f+1) if f < total_b else 0
// d_out layout: [B*ML*D floats (out)] then [B*ML floats (mel_pos as float)]

#define TPB 256
#define FPB 32
#define B_FIXED 32
#define T_FIXED 512
#define D_FIXED 384
#define ML_FIXED 4096
#define QV 96   // D/4 float4s per frame

__global__ void __launch_bounds__(TPB)
length_regulator_kernel(const float* __restrict__ x,
                        const int* __restrict__ dur,
                        float* __restrict__ out,
                        float* __restrict__ melpos)
{
    __shared__ int cum[T_FIXED];
    __shared__ int warp_off[8];
    __shared__ int s_tok[FPB];
    __shared__ int s_valid[FPB];

    const int b    = blockIdx.y;
    const int t    = threadIdx.x;
    const int lane = t & 31;
    const int w    = t >> 5;

    // ---- inclusive prefix sum of dur[b, :] (512 elems, 2 per thread) ----
    int2 dd = ((const int2*)(dur + b * T_FIXED))[t];
    const int d0 = dd.x, d1 = dd.y;
    const int pair = d0 + d1;

    // warp-inclusive scan of pair sums
    int v = pair;
    #pragma unroll
    for (int off = 1; off < 32; off <<= 1) {
        int n = __shfl_up_sync(0xFFFFFFFFu, v, off);
        if (lane >= off) v += n;
    }
    if (lane == 31) warp_off[w] = v;   // warp totals
    __syncthreads();

    if (t < 8) {
        int wv = warp_off[t];
        #pragma unroll
        for (int off = 1; off < 8; off <<= 1) {
            int n = __shfl_up_sync(0x000000FFu, wv, off);
            if (t >= off) wv += n;
        }
        warp_off[t] = wv - warp_off[t];  // exclusive scan of warp totals
    }
    __syncthreads();

    const int excl = warp_off[w] + (v - pair);  // exclusive prefix of pairs
    cum[2 * t]     = excl + d0;
    cum[2 * t + 1] = excl + d0 + d1;
    __syncthreads();

    const int total = cum[T_FIXED - 1];
    const int f0 = blockIdx.x * FPB;

    // ---- per-frame token index: first i with cum[i] > f (searchsorted right) ----
    if (t < FPB) {
        const int f = f0 + t;
        int lo = 0, hi = T_FIXED;
        // NOTE: 10 iterations required — interval must reach 0, not 1.
        // (9 iterations leave hi-lo==1 on some paths with cum[lo] undetermined.)
        #pragma unroll
        for (int step = 0; step < 10; ++step) {
            if (lo < hi) {
                int mid = (lo + hi) >> 1;
                if (cum[mid] <= f) lo = mid + 1; else hi = mid;
            }
        }
        int tok   = (lo < T_FIXED - 1) ? lo : (T_FIXED - 1);
        int valid = (f < total);
        s_tok[t]   = tok;
        s_valid[t] = valid;
        melpos[(size_t)b * ML_FIXED + f] = valid ? (float)(f + 1) : 0.0f;
    }
    __syncthreads();

    // ---- vectorized gather/scatter: FPB frames x QV float4 ----
    const float4* __restrict__ x4 = (const float4*)(x + (size_t)b * T_FIXED * D_FIXED);
    float4* __restrict__ o4 = (float4*)(out + ((size_t)b * ML_FIXED + f0) * D_FIXED);
    const float4 zero = make_float4(0.f, 0.f, 0.f, 0.f);

    #pragma unroll 4
    for (int i = t; i < FPB * QV; i += TPB) {
        int fr = i / QV;
        int q  = i - fr * QV;
        float4 val = s_valid[fr] ? x4[(size_t)s_tok[fr] * QV + q] : zero;
        o4[(size_t)fr * QV + q] = val;
    }
}

extern "C" void kernel_launch(void* const* d_in, const int* in_sizes, int n_in,
                              void* d_out, int out_size)
{
    const float* x   = (const float*)d_in[0];
    const int*   dur = (const int*)d_in[1];

    float* out    = (float*)d_out;
    float* melpos = out + (size_t)B_FIXED * ML_FIXED * D_FIXED;

    dim3 grid(ML_FIXED / FPB, B_FIXED);
    length_regulator_kernel<<<grid, TPB>>>(x, dur, out, melpos);
}

// round 6
// speedup vs baseline: 1.0924x; 1.0924x over previous
#include <cuda_runtime.h>

// LengthRegulator, fixed shapes: B=32, T=512, D=384, ML=4096.
// Split design:
//   K1 (precompute, 32 blocks): per-batch cumsum + searchsorted for all 4096
//      frames -> packed (tok | valid<<16) in __device__ scratch; writes mel_pos.
//   K2 (scatter, 4096 blocks): pure streaming gather/store, fully unrolled.
// d_out layout: [B*ML*D floats (out)] then [B*ML floats (mel_pos as float)]

#define B_FIXED 32
#define T_FIXED 512
#define D_FIXED 384
#define ML_FIXED 4096
#define QV 96            // D/4 float4 per frame
#define TPB 256
#define FPB 32           // frames per scatter block

__device__ int g_tokpack[B_FIXED * ML_FIXED];   // tok | (valid<<16)

// ---------------- K1: precompute ----------------
__global__ void __launch_bounds__(T_FIXED)
lr_precompute(const int* __restrict__ dur, float* __restrict__ melpos)
{
    __shared__ int cum[T_FIXED];
    __shared__ int woff[16];

    const int b = blockIdx.x;
    const int t = threadIdx.x;           // 512 threads, one duration each
    const int lane = t & 31;
    const int w = t >> 5;

    int d = dur[b * T_FIXED + t];
    int v = d;
    #pragma unroll
    for (int off = 1; off < 32; off <<= 1) {
        int n = __shfl_up_sync(0xFFFFFFFFu, v, off);
        if (lane >= off) v += n;
    }
    if (lane == 31) woff[w] = v;
    __syncthreads();
    if (t < 16) {
        int wv = woff[t];
        #pragma unroll
        for (int off = 1; off < 16; off <<= 1) {
            int n = __shfl_up_sync(0x0000FFFFu, wv, off);
            if (t >= off) wv += n;
        }
        woff[t] = wv - woff[t];          // exclusive scan of warp totals
    }
    __syncthreads();
    cum[t] = v + woff[w];                // inclusive cumsum
    __syncthreads();

    const int total = cum[T_FIXED - 1];

    #pragma unroll
    for (int j = 0; j < ML_FIXED / T_FIXED; ++j) {     // 8 frames per thread
        const int f = j * T_FIXED + t;                 // coalesced across t
        int lo = 0, hi = T_FIXED;
        #pragma unroll
        for (int step = 0; step < 10; ++step) {        // interval must reach 0
            if (lo < hi) {
                int mid = (lo + hi) >> 1;
                if (cum[mid] <= f) lo = mid + 1; else hi = mid;
            }
        }
        int tok   = (lo < T_FIXED - 1) ? lo : (T_FIXED - 1);
        int valid = (f < total);
        g_tokpack[b * ML_FIXED + f] = tok | (valid << 16);
        melpos[(size_t)b * ML_FIXED + f] = valid ? (float)(f + 1) : 0.0f;
    }
}

// ---------------- K2: streaming scatter ----------------
__global__ void __launch_bounds__(TPB)
lr_scatter(const float* __restrict__ x, float* __restrict__ out)
{
    __shared__ int s_tp[FPB];

    const int b  = blockIdx.y;
    const int f0 = blockIdx.x * FPB;
    const int t  = threadIdx.x;

    if (t < FPB) s_tp[t] = g_tokpack[b * ML_FIXED + f0 + t];
    __syncthreads();

    const float4* __restrict__ x4 = (const float4*)(x + (size_t)b * T_FIXED * D_FIXED);
    float4* __restrict__ o4 = (float4*)(out + ((size_t)b * ML_FIXED + f0) * D_FIXED);
    const float4 zero = make_float4(0.f, 0.f, 0.f, 0.f);

    // 32 frames x 96 float4 = 3072 stores; 12 per thread, fully unrolled.
    #pragma unroll
    for (int j = 0; j < 12; ++j) {
        const int i  = j * TPB + t;
        const int fr = i / QV;           // const-divide -> mul/shift
        const int q  = i - fr * QV;
        const int tp = s_tp[fr];
        float4 val = (tp >> 16) ? x4[(size_t)(tp & 0xFFFF) * QV + q] : zero;
        // streaming store: evict-first, keep x resident in L2
        __stcs(&o4[(size_t)fr * QV + q], val);
    }
}

extern "C" void kernel_launch(void* const* d_in, const int* in_sizes, int n_in,
                              void* d_out, int out_size)
{
    const float* x   = (const float*)d_in[0];
    const int*   dur = (const int*)d_in[1];

    float* out    = (float*)d_out;
    float* melpos = out + (size_t)B_FIXED * ML_FIXED * D_FIXED;

    lr_precompute<<<B_FIXED, T_FIXED>>>(dur, melpos);
    dim3 grid(ML_FIXED / FPB, B_FIXED);
    lr_scatter<<<grid, TPB>>>(x, out);
}